// round 2
// baseline (speedup 1.0000x reference)
#include <cuda_runtime.h>
#include <math.h>

#define BB 4
#define LL 2048
#define DM 512
#define NH 2
#define DK 64
#define HD 128            // NH*DK
#define OUT0 (BB*LL*DM)   // 4194304 floats; attn follows

// scratch (static device globals — no allocations)
__device__ float g_q[BB*LL*HD];
__device__ float g_k[BB*LL*HD];
__device__ float g_v[BB*LL*HD];
__device__ float g_oh[BB*LL*HD];

// ---------------------------------------------------------------------------
// Generic tiled GEMM: C[M,N] = A[M,K] @ W[K,N] + bias[N]
// 64x64 C tile, BK=16, 256 threads, 4x4 per thread. M,N multiples of 64, K of 16.
// ---------------------------------------------------------------------------
__global__ __launch_bounds__(256) void gemm_bias_kernel(
    const float* __restrict__ A, const float* __restrict__ W,
    const float* __restrict__ bias, float* __restrict__ C,
    int M, int N, int K)
{
    __shared__ float As[16][65];
    __shared__ float Ws[16][65];
    const int tid = threadIdx.x;
    const int bm = blockIdx.y * 64, bn = blockIdx.x * 64;
    const int ty = tid >> 4, tx = tid & 15;
    float acc[4][4] = {};
    for (int k0 = 0; k0 < K; k0 += 16) {
#pragma unroll
        for (int r = 0; r < 4; r++) {
            int idx = tid + r * 256;
            int m = idx >> 4, k = idx & 15;
            As[k][m] = A[(size_t)(bm + m) * K + k0 + k];
        }
#pragma unroll
        for (int r = 0; r < 4; r++) {
            int idx = tid + r * 256;
            int k = idx >> 6, n = idx & 63;
            Ws[k][n] = W[(size_t)(k0 + k) * N + bn + n];
        }
        __syncthreads();
#pragma unroll
        for (int kk = 0; kk < 16; kk++) {
            float a[4], b[4];
#pragma unroll
            for (int i = 0; i < 4; i++) a[i] = As[kk][ty + 16 * i];
#pragma unroll
            for (int j = 0; j < 4; j++) b[j] = Ws[kk][tx + 16 * j];
#pragma unroll
            for (int i = 0; i < 4; i++)
#pragma unroll
                for (int j = 0; j < 4; j++)
                    acc[i][j] += a[i] * b[j];
        }
        __syncthreads();
    }
#pragma unroll
    for (int i = 0; i < 4; i++) {
        int m = bm + ty + 16 * i;
#pragma unroll
        for (int j = 0; j < 4; j++) {
            int n = bn + tx + 16 * j;
            C[(size_t)m * N + n] = acc[i][j] + bias[n];
        }
    }
}

// ---------------------------------------------------------------------------
// Scores: for (b,h), S[i,j] = tanh(dot(q_i,k_j)/8)*10, masked -> -10
// 64x64 tile per block, full d=64 in smem. Writes raw clipped scores to attn.
// mask is int32 (bool promoted by harness).
// ---------------------------------------------------------------------------
__global__ __launch_bounds__(256) void scores_kernel(
    const float* __restrict__ q, const float* __restrict__ k,
    const int* __restrict__ mask, float* __restrict__ attn)
{
    __shared__ float Qs[64][65];
    __shared__ float Ks[64][65];
    const int bh = blockIdx.z;          // 0..7  (b*2+h)
    const int b = bh >> 1, h = bh & 1;
    const int i0 = blockIdx.y * 64, j0 = blockIdx.x * 64;
    const int tid = threadIdx.x;
#pragma unroll
    for (int r = 0; r < 16; r++) {
        int idx = tid + r * 256;
        int m = idx >> 6, d = idx & 63;
        Qs[d][m] = q[(size_t)(b * LL + i0 + m) * HD + h * DK + d];
        Ks[d][m] = k[(size_t)(b * LL + j0 + m) * HD + h * DK + d];
    }
    __syncthreads();
    const int ty = tid >> 4, tx = tid & 15;
    float acc[4][4] = {};
#pragma unroll
    for (int d = 0; d < 64; d++) {
        float a[4], bb[4];
#pragma unroll
        for (int i = 0; i < 4; i++) a[i] = Qs[d][ty + 16 * i];
#pragma unroll
        for (int j = 0; j < 4; j++) bb[j] = Ks[d][tx + 16 * j];
#pragma unroll
        for (int i = 0; i < 4; i++)
#pragma unroll
            for (int j = 0; j < 4; j++)
                acc[i][j] += a[i] * bb[j];
    }
#pragma unroll
    for (int j = 0; j < 4; j++) {
        int jj = j0 + tx + 16 * j;
        bool msk = mask[b * LL + jj] != 0;
#pragma unroll
        for (int i = 0; i < 4; i++) {
            int ii = i0 + ty + 16 * i;
            float s = tanhf(acc[i][j] * 0.125f) * 10.0f;
            if (msk) s = -10.0f;
            attn[((size_t)bh * LL + ii) * LL + jj] = s;
        }
    }
}

// ---------------------------------------------------------------------------
// In-place log-softmax over each 2048-wide row: x -> x - max - log(sum exp(x-max))
// One block (256 threads) per row, float4 loads.
// ---------------------------------------------------------------------------
__global__ __launch_bounds__(256) void logsoftmax_kernel(float* __restrict__ attn)
{
    __shared__ float red[8];
    __shared__ float bcast;
    const int tid = threadIdx.x;
    float* p = attn + (size_t)blockIdx.x * LL;
    float4 a = reinterpret_cast<const float4*>(p)[tid];
    float4 b = reinterpret_cast<const float4*>(p)[tid + 256];

    float m = fmaxf(fmaxf(fmaxf(a.x, a.y), fmaxf(a.z, a.w)),
                    fmaxf(fmaxf(b.x, b.y), fmaxf(b.z, b.w)));
#pragma unroll
    for (int o = 16; o; o >>= 1) m = fmaxf(m, __shfl_xor_sync(0xffffffffu, m, o));
    if ((tid & 31) == 0) red[tid >> 5] = m;
    __syncthreads();
    if (tid < 32) {
        float t = (tid < 8) ? red[tid] : -3.0e38f;
#pragma unroll
        for (int o = 4; o; o >>= 1) t = fmaxf(t, __shfl_xor_sync(0xffffffffu, t, o));
        if (tid == 0) bcast = t;
    }
    __syncthreads();
    m = bcast;

    float s = expf(a.x - m) + expf(a.y - m) + expf(a.z - m) + expf(a.w - m)
            + expf(b.x - m) + expf(b.y - m) + expf(b.z - m) + expf(b.w - m);
#pragma unroll
    for (int o = 16; o; o >>= 1) s += __shfl_xor_sync(0xffffffffu, s, o);
    __syncthreads();
    if ((tid & 31) == 0) red[tid >> 5] = s;
    __syncthreads();
    if (tid < 32) {
        float t = (tid < 8) ? red[tid] : 0.0f;
#pragma unroll
        for (int o = 4; o; o >>= 1) t += __shfl_xor_sync(0xffffffffu, t, o);
        if (tid == 0) bcast = m + logf(t);
    }
    __syncthreads();
    const float lse = bcast;

    a.x -= lse; a.y -= lse; a.z -= lse; a.w -= lse;
    b.x -= lse; b.y -= lse; b.z -= lse; b.w -= lse;
    reinterpret_cast<float4*>(p)[tid] = a;
    reinterpret_cast<float4*>(p)[tid + 256] = b;
}

// ---------------------------------------------------------------------------
// oh[b, i, h*64+d] = sum_j attn[b,h,i,j] * v[b, j, h*64+d]
// 32(i) x 64(d) tile per block, BK=64 over j. 512 blocks total.
// ---------------------------------------------------------------------------
__global__ __launch_bounds__(256) void av_kernel(
    const float* __restrict__ attn, const float* __restrict__ v,
    float* __restrict__ oh)
{
    __shared__ float As[64][33];   // [j][i]
    __shared__ float Vs[64][65];   // [j][d]
    const int bh = blockIdx.z;
    const int b = bh >> 1, h = bh & 1;
    const int i0 = blockIdx.y * 32;
    const int tid = threadIdx.x;
    const int ty = tid >> 4, tx = tid & 15;
    float acc[2][4] = {};
    for (int k0 = 0; k0 < LL; k0 += 64) {
#pragma unroll
        for (int r = 0; r < 8; r++) {
            int idx = tid + r * 256;      // 2048 elems: 32 x 64
            int m = idx >> 6, kk = idx & 63;
            As[kk][m] = attn[((size_t)bh * LL + i0 + m) * LL + k0 + kk];
        }
#pragma unroll
        for (int r = 0; r < 16; r++) {
            int idx = tid + r * 256;      // 4096 elems: 64 x 64
            int kk = idx >> 6, n = idx & 63;
            Vs[kk][n] = v[(size_t)(b * LL + k0 + kk) * HD + h * DK + n];
        }
        __syncthreads();
#pragma unroll
        for (int kk = 0; kk < 64; kk++) {
            float a[2], bb[4];
#pragma unroll
            for (int i = 0; i < 2; i++) a[i] = As[kk][ty + 16 * i];
#pragma unroll
            for (int j = 0; j < 4; j++) bb[j] = Vs[kk][tx + 16 * j];
#pragma unroll
            for (int i = 0; i < 2; i++)
#pragma unroll
                for (int j = 0; j < 4; j++)
                    acc[i][j] += a[i] * bb[j];
        }
        __syncthreads();
    }
#pragma unroll
    for (int i = 0; i < 2; i++) {
        int ii = i0 + ty + 16 * i;
#pragma unroll
        for (int j = 0; j < 4; j++) {
            int d = tx + 16 * j;
            oh[(size_t)(b * LL + ii) * HD + h * DK + d] = acc[i][j];
        }
    }
}

// ---------------------------------------------------------------------------
extern "C" void kernel_launch(void* const* d_in, const int* in_sizes, int n_in,
                              void* d_out, int out_size)
{
    const float* Q  = (const float*)d_in[0];
    const float* K  = (const float*)d_in[1];
    const float* V  = (const float*)d_in[2];
    const int*   mask = (const int*)d_in[3];
    const float* Wq = (const float*)d_in[4];
    const float* bq = (const float*)d_in[5];
    const float* Wk = (const float*)d_in[6];
    const float* bk = (const float*)d_in[7];
    const float* Wv = (const float*)d_in[8];
    const float* bv = (const float*)d_in[9];
    const float* Wo = (const float*)d_in[10];
    const float* bo = (const float*)d_in[11];

    float* out  = (float*)d_out;          // [B, Lq, 512]
    float* attn = out + OUT0;             // [B, H, Lq, Lk]

    float *q, *k, *v, *oh;
    cudaGetSymbolAddress((void**)&q,  g_q);
    cudaGetSymbolAddress((void**)&k,  g_k);
    cudaGetSymbolAddress((void**)&v,  g_v);
    cudaGetSymbolAddress((void**)&oh, g_oh);

    const int M = BB * LL;                // 8192

    // 1) projections: [8192,512] @ [512,128]
    dim3 gp(HD / 64, M / 64);
    gemm_bias_kernel<<<gp, 256>>>(Q, Wq, bq, q, M, HD, DM);
    gemm_bias_kernel<<<gp, 256>>>(K, Wk, bk, k, M, HD, DM);
    gemm_bias_kernel<<<gp, 256>>>(V, Wv, bv, v, M, HD, DM);

    // 2) scores + tanh clip + mask  -> attn (raw)
    dim3 gs(LL / 64, LL / 64, BB * NH);
    scores_kernel<<<gs, 256>>>(q, k, mask, attn);

    // 3) row log-softmax in place
    logsoftmax_kernel<<<BB * NH * LL, 256>>>(attn);

    // 4) attn @ v -> oh [8192,128]
    dim3 ga(1, LL / 32, BB * NH);
    av_kernel<<<ga, 256>>>(attn, v, oh);

    // 5) out = oh @ Wo + bo : [8192,128] @ [128,512]
    dim3 go(DM / 64, M / 64);
    gemm_bias_kernel<<<go, 256>>>(oh, Wo, bo, out, M, DM, HD);
}

// round 3
// speedup vs baseline: 1.3633x; 1.3633x over previous
#include <cuda_runtime.h>
#include <math.h>

#define BB 4
#define LL 2048
#define DM 512
#define NH 2
#define DK 64
#define HD 128            // NH*DK
#define OUT0 (BB*LL*DM)   // 4194304 floats; attn follows

// scratch (static device globals — no allocations)
__device__ float g_q[BB*LL*HD];
__device__ float g_k[BB*LL*HD];
__device__ float g_v[BB*LL*HD];
__device__ float g_oh[BB*LL*HD];

// ---------------------------------------------------------------------------
// Generic tiled GEMM: C[M,N] = A[M,K] @ W[K,N] + bias[N]
// 64x64 C tile, BK=16, 256 threads, 4x4 per thread, float4 fragments.
// M,N multiples of 64, K multiple of 16.
// ---------------------------------------------------------------------------
__global__ __launch_bounds__(256) void gemm_bias_kernel(
    const float* __restrict__ A, const float* __restrict__ W,
    const float* __restrict__ bias, float* __restrict__ C,
    int M, int N, int K)
{
    __shared__ float As[16][68];   // [k][m]
    __shared__ float Ws[16][68];   // [k][n]
    const int tid = threadIdx.x;
    const int bm = blockIdx.y * 64, bn = blockIdx.x * 64;
    const int ty = tid >> 4, tx = tid & 15;
    float acc[4][4] = {};

    for (int k0 = 0; k0 < K; k0 += 16) {
        // A tile 64x16 -> transposed store. 256 float4, one per thread.
        {
            int m = tid >> 2, k4 = tid & 3;
            float4 t = *reinterpret_cast<const float4*>(
                &A[(size_t)(bm + m) * K + k0 + k4 * 4]);
            As[k4 * 4 + 0][m] = t.x;
            As[k4 * 4 + 1][m] = t.y;
            As[k4 * 4 + 2][m] = t.z;
            As[k4 * 4 + 3][m] = t.w;
        }
        // W tile 16x64 -> direct. 256 float4, one per thread.
        {
            int kk = tid >> 4, n4 = tid & 15;
            *reinterpret_cast<float4*>(&Ws[kk][n4 * 4]) =
                *reinterpret_cast<const float4*>(
                    &W[(size_t)(k0 + kk) * N + bn + n4 * 4]);
        }
        __syncthreads();
#pragma unroll
        for (int kk = 0; kk < 16; kk++) {
            float4 a = *reinterpret_cast<const float4*>(&As[kk][ty * 4]);
            float4 b = *reinterpret_cast<const float4*>(&Ws[kk][tx * 4]);
            float av[4] = {a.x, a.y, a.z, a.w};
            float bv[4] = {b.x, b.y, b.z, b.w};
#pragma unroll
            for (int i = 0; i < 4; i++)
#pragma unroll
                for (int j = 0; j < 4; j++)
                    acc[i][j] += av[i] * bv[j];
        }
        __syncthreads();
    }
    float4 bs = *reinterpret_cast<const float4*>(&bias[bn + tx * 4]);
#pragma unroll
    for (int i = 0; i < 4; i++) {
        int m = bm + ty * 4 + i;
        float4 o = make_float4(acc[i][0] + bs.x, acc[i][1] + bs.y,
                               acc[i][2] + bs.z, acc[i][3] + bs.w);
        *reinterpret_cast<float4*>(&C[(size_t)m * N + bn + tx * 4]) = o;
    }
}

// ---------------------------------------------------------------------------
// Scores: for (b,h), S[i,j] = tanh(dot(q_i,k_j)/8)*10, masked -> -10
// 128x128 tile per block, 8x8 per thread, BK=16 over d (4 chunks).
// Writes raw clipped scores to attn. mask is int32.
// ---------------------------------------------------------------------------
__global__ __launch_bounds__(256) void scores_kernel(
    const float* __restrict__ q, const float* __restrict__ k,
    const int* __restrict__ mask, float* __restrict__ attn)
{
    __shared__ float Qs[16][132];  // [d][i]
    __shared__ float Ks[16][132];  // [d][j]
    const int bh = blockIdx.z;     // 0..7  (b*2+h)
    const int b = bh >> 1, h = bh & 1;
    const int i0 = blockIdx.y * 128, j0 = blockIdx.x * 128;
    const int tid = threadIdx.x;
    const int ty = tid >> 4, tx = tid & 15;
    float acc[8][8] = {};

    for (int k0 = 0; k0 < DK; k0 += 16) {
#pragma unroll
        for (int r = 0; r < 2; r++) {
            int idx = tid + r * 256;        // 512 float4 (128 rows x 4 f4)
            int m = idx >> 2, k4 = idx & 3;
            float4 tq = *reinterpret_cast<const float4*>(
                &q[(size_t)(b * LL + i0 + m) * HD + h * DK + k0 + k4 * 4]);
            Qs[k4 * 4 + 0][m] = tq.x;
            Qs[k4 * 4 + 1][m] = tq.y;
            Qs[k4 * 4 + 2][m] = tq.z;
            Qs[k4 * 4 + 3][m] = tq.w;
            float4 tk = *reinterpret_cast<const float4*>(
                &k[(size_t)(b * LL + j0 + m) * HD + h * DK + k0 + k4 * 4]);
            Ks[k4 * 4 + 0][m] = tk.x;
            Ks[k4 * 4 + 1][m] = tk.y;
            Ks[k4 * 4 + 2][m] = tk.z;
            Ks[k4 * 4 + 3][m] = tk.w;
        }
        __syncthreads();
#pragma unroll
        for (int kk = 0; kk < 16; kk++) {
            float4 a0 = *reinterpret_cast<const float4*>(&Qs[kk][ty * 4]);
            float4 a1 = *reinterpret_cast<const float4*>(&Qs[kk][64 + ty * 4]);
            float4 b0 = *reinterpret_cast<const float4*>(&Ks[kk][tx * 4]);
            float4 b1 = *reinterpret_cast<const float4*>(&Ks[kk][64 + tx * 4]);
            float av[8] = {a0.x, a0.y, a0.z, a0.w, a1.x, a1.y, a1.z, a1.w};
            float bv[8] = {b0.x, b0.y, b0.z, b0.w, b1.x, b1.y, b1.z, b1.w};
#pragma unroll
            for (int i = 0; i < 8; i++)
#pragma unroll
                for (int j = 0; j < 8; j++)
                    acc[i][j] += av[i] * bv[j];
        }
        __syncthreads();
    }

    const int jj0 = j0 + tx * 4;
    const int jj1 = j0 + 64 + tx * 4;
    int4 m0 = *reinterpret_cast<const int4*>(&mask[b * LL + jj0]);
    int4 m1 = *reinterpret_cast<const int4*>(&mask[b * LL + jj1]);
#pragma unroll
    for (int i = 0; i < 8; i++) {
        int ii = i0 + ((i < 4) ? (ty * 4 + i) : (64 + ty * 4 + i - 4));
        float4 o0, o1;
        o0.x = m0.x ? -10.0f : tanhf(acc[i][0] * 0.125f) * 10.0f;
        o0.y = m0.y ? -10.0f : tanhf(acc[i][1] * 0.125f) * 10.0f;
        o0.z = m0.z ? -10.0f : tanhf(acc[i][2] * 0.125f) * 10.0f;
        o0.w = m0.w ? -10.0f : tanhf(acc[i][3] * 0.125f) * 10.0f;
        o1.x = m1.x ? -10.0f : tanhf(acc[i][4] * 0.125f) * 10.0f;
        o1.y = m1.y ? -10.0f : tanhf(acc[i][5] * 0.125f) * 10.0f;
        o1.z = m1.z ? -10.0f : tanhf(acc[i][6] * 0.125f) * 10.0f;
        o1.w = m1.w ? -10.0f : tanhf(acc[i][7] * 0.125f) * 10.0f;
        float* row = &attn[((size_t)bh * LL + ii) * LL];
        *reinterpret_cast<float4*>(&row[jj0]) = o0;
        *reinterpret_cast<float4*>(&row[jj1]) = o1;
    }
}

// ---------------------------------------------------------------------------
// In-place log-softmax over each 2048-wide row.
// ---------------------------------------------------------------------------
__global__ __launch_bounds__(256) void logsoftmax_kernel(float* __restrict__ attn)
{
    __shared__ float red[8];
    __shared__ float bcast;
    const int tid = threadIdx.x;
    float* p = attn + (size_t)blockIdx.x * LL;
    float4 a = reinterpret_cast<const float4*>(p)[tid];
    float4 b = reinterpret_cast<const float4*>(p)[tid + 256];

    float m = fmaxf(fmaxf(fmaxf(a.x, a.y), fmaxf(a.z, a.w)),
                    fmaxf(fmaxf(b.x, b.y), fmaxf(b.z, b.w)));
#pragma unroll
    for (int o = 16; o; o >>= 1) m = fmaxf(m, __shfl_xor_sync(0xffffffffu, m, o));
    if ((tid & 31) == 0) red[tid >> 5] = m;
    __syncthreads();
    if (tid < 32) {
        float t = (tid < 8) ? red[tid] : -3.0e38f;
#pragma unroll
        for (int o = 4; o; o >>= 1) t = fmaxf(t, __shfl_xor_sync(0xffffffffu, t, o));
        if (tid == 0) bcast = t;
    }
    __syncthreads();
    m = bcast;

    float s = expf(a.x - m) + expf(a.y - m) + expf(a.z - m) + expf(a.w - m)
            + expf(b.x - m) + expf(b.y - m) + expf(b.z - m) + expf(b.w - m);
#pragma unroll
    for (int o = 16; o; o >>= 1) s += __shfl_xor_sync(0xffffffffu, s, o);
    __syncthreads();
    if ((tid & 31) == 0) red[tid >> 5] = s;
    __syncthreads();
    if (tid < 32) {
        float t = (tid < 8) ? red[tid] : 0.0f;
#pragma unroll
        for (int o = 4; o; o >>= 1) t += __shfl_xor_sync(0xffffffffu, t, o);
        if (tid == 0) bcast = m + logf(t);
    }
    __syncthreads();
    const float lse = bcast;

    a.x -= lse; a.y -= lse; a.z -= lse; a.w -= lse;
    b.x -= lse; b.y -= lse; b.z -= lse; b.w -= lse;
    reinterpret_cast<float4*>(p)[tid] = a;
    reinterpret_cast<float4*>(p)[tid + 256] = b;
}

// ---------------------------------------------------------------------------
// oh[b, i, h*64+d] = sum_j attn[b,h,i,j] * v[b, j, h*64+d]
// 64(i) x 64(d) tile per block, 4x4 per thread, BK=32 over j. 256 blocks.
// ---------------------------------------------------------------------------
__global__ __launch_bounds__(256) void av_kernel(
    const float* __restrict__ attn, const float* __restrict__ v,
    float* __restrict__ oh)
{
    __shared__ float As[32][68];   // [j][i]
    __shared__ float Vs[32][68];   // [j][d]
    const int bh = blockIdx.y;
    const int b = bh >> 1, h = bh & 1;
    const int i0 = blockIdx.x * 64;
    const int tid = threadIdx.x;
    const int ty = tid >> 4, tx = tid & 15;
    float acc[4][4] = {};

    for (int k0 = 0; k0 < LL; k0 += 32) {
#pragma unroll
        for (int r = 0; r < 2; r++) {
            int idx = tid + r * 256;      // 512 float4: 64 rows x 8 f4
            int i = idx >> 3, j4 = idx & 7;
            float4 t = *reinterpret_cast<const float4*>(
                &attn[((size_t)bh * LL + i0 + i) * LL + k0 + j4 * 4]);
            As[j4 * 4 + 0][i] = t.x;
            As[j4 * 4 + 1][i] = t.y;
            As[j4 * 4 + 2][i] = t.z;
            As[j4 * 4 + 3][i] = t.w;
        }
#pragma unroll
        for (int r = 0; r < 2; r++) {
            int idx = tid + r * 256;      // 512 float4: 32 rows x 16 f4
            int jj = idx >> 4, d4 = idx & 15;
            *reinterpret_cast<float4*>(&Vs[jj][d4 * 4]) =
                *reinterpret_cast<const float4*>(
                    &v[(size_t)(b * LL + k0 + jj) * HD + h * DK + d4 * 4]);
        }
        __syncthreads();
#pragma unroll
        for (int kk = 0; kk < 32; kk++) {
            float4 a = *reinterpret_cast<const float4*>(&As[kk][ty * 4]);
            float4 bb = *reinterpret_cast<const float4*>(&Vs[kk][tx * 4]);
            float av[4] = {a.x, a.y, a.z, a.w};
            float bv[4] = {bb.x, bb.y, bb.z, bb.w};
#pragma unroll
            for (int i = 0; i < 4; i++)
#pragma unroll
                for (int j = 0; j < 4; j++)
                    acc[i][j] += av[i] * bv[j];
        }
        __syncthreads();
    }
#pragma unroll
    for (int i = 0; i < 4; i++) {
        int ii = i0 + ty * 4 + i;
        float4 o = make_float4(acc[i][0], acc[i][1], acc[i][2], acc[i][3]);
        *reinterpret_cast<float4*>(
            &oh[(size_t)(b * LL + ii) * HD + h * DK + tx * 4]) = o;
    }
}

// ---------------------------------------------------------------------------
extern "C" void kernel_launch(void* const* d_in, const int* in_sizes, int n_in,
                              void* d_out, int out_size)
{
    const float* Q  = (const float*)d_in[0];
    const float* K  = (const float*)d_in[1];
    const float* V  = (const float*)d_in[2];
    const int*   mask = (const int*)d_in[3];
    const float* Wq = (const float*)d_in[4];
    const float* bq = (const float*)d_in[5];
    const float* Wk = (const float*)d_in[6];
    const float* bk = (const float*)d_in[7];
    const float* Wv = (const float*)d_in[8];
    const float* bv = (const float*)d_in[9];
    const float* Wo = (const float*)d_in[10];
    const float* bo = (const float*)d_in[11];

    float* out  = (float*)d_out;          // [B, Lq, 512]
    float* attn = out + OUT0;             // [B, H, Lq, Lk]

    float *q, *k, *v, *oh;
    cudaGetSymbolAddress((void**)&q,  g_q);
    cudaGetSymbolAddress((void**)&k,  g_k);
    cudaGetSymbolAddress((void**)&v,  g_v);
    cudaGetSymbolAddress((void**)&oh, g_oh);

    const int M = BB * LL;                // 8192

    // 1) projections: [8192,512] @ [512,128]
    dim3 gp(HD / 64, M / 64);
    gemm_bias_kernel<<<gp, 256>>>(Q, Wq, bq, q, M, HD, DM);
    gemm_bias_kernel<<<gp, 256>>>(K, Wk, bk, k, M, HD, DM);
    gemm_bias_kernel<<<gp, 256>>>(V, Wv, bv, v, M, HD, DM);

    // 2) scores + tanh clip + mask  -> attn (raw)
    dim3 gs(LL / 128, LL / 128, BB * NH);
    scores_kernel<<<gs, 256>>>(q, k, mask, attn);

    // 3) row log-softmax in place
    logsoftmax_kernel<<<BB * NH * LL, 256>>>(attn);

    // 4) attn @ v -> oh [8192,128]
    dim3 ga(LL / 64, BB * NH);
    av_kernel<<<ga, 256>>>(attn, v, oh);

    // 5) out = oh @ Wo + bo : [8192,128] @ [128,512]
    dim3 go(DM / 64, M / 64);
    gemm_bias_kernel<<<go, 256>>>(oh, Wo, bo, out, M, DM, HD);
}

// round 4
// speedup vs baseline: 1.5890x; 1.1655x over previous
#include <cuda_runtime.h>
#include <math.h>

#define BB 4
#define LL 2048
#define DM 512
#define NH 2
#define DK 64
#define HD 128            // NH*DK
#define OUT0 (BB*LL*DM)   // 4194304 floats; attn follows
#define NROWS (BB*NH*LL)  // 16384 attention rows

// scratch (static device globals — no allocations)
__device__ float g_q[BB*LL*HD];
__device__ float g_k[BB*LL*HD];
__device__ float g_v[BB*LL*HD];
__device__ float g_oh[BB*LL*HD];
__device__ float g_rowsum[NROWS];   // sum exp(s) per row, then lse in place

__device__ __forceinline__ float fast_tanh(float x) {
    float y;
    asm("tanh.approx.f32 %0, %1;" : "=f"(y) : "f"(x));
    return y;
}

// ---------------------------------------------------------------------------
__global__ __launch_bounds__(256) void zero_rowsum_kernel(float* __restrict__ rs)
{
    rs[blockIdx.x * 256 + threadIdx.x] = 0.0f;
}

__global__ __launch_bounds__(256) void lse_kernel(float* __restrict__ rs)
{
    int i = blockIdx.x * 256 + threadIdx.x;
    rs[i] = logf(rs[i]);
}

// ---------------------------------------------------------------------------
// Tiled GEMM: C[M,N] = A[M,K] @ W[K,N] + bias[N]
// 128x64 C tile, BK=16, 256 threads, 8x4 per thread, float4 fragments.
// ---------------------------------------------------------------------------
__global__ __launch_bounds__(256) void gemm_bias_kernel(
    const float* __restrict__ A, const float* __restrict__ W,
    const float* __restrict__ bias, float* __restrict__ C,
    int M, int N, int K)
{
    __shared__ float As[16][132];  // [k][m], m=0..127
    __shared__ float Ws[16][68];   // [k][n]
    const int tid = threadIdx.x;
    const int bm = blockIdx.y * 128, bn = blockIdx.x * 64;
    const int ty = tid >> 4, tx = tid & 15;
    float acc[8][4] = {};

    for (int k0 = 0; k0 < K; k0 += 16) {
#pragma unroll
        for (int r = 0; r < 2; r++) {           // 512 f4: 128 rows x 4 f4
            int idx = tid + r * 256;
            int m = idx >> 2, k4 = idx & 3;
            float4 t = *reinterpret_cast<const float4*>(
                &A[(size_t)(bm + m) * K + k0 + k4 * 4]);
            As[k4 * 4 + 0][m] = t.x;
            As[k4 * 4 + 1][m] = t.y;
            As[k4 * 4 + 2][m] = t.z;
            As[k4 * 4 + 3][m] = t.w;
        }
        {                                        // 256 f4: 16 rows x 16 f4
            int kk = tid >> 4, n4 = tid & 15;
            *reinterpret_cast<float4*>(&Ws[kk][n4 * 4]) =
                *reinterpret_cast<const float4*>(
                    &W[(size_t)(k0 + kk) * N + bn + n4 * 4]);
        }
        __syncthreads();
#pragma unroll
        for (int kk = 0; kk < 16; kk++) {
            float4 a0 = *reinterpret_cast<const float4*>(&As[kk][ty * 4]);
            float4 a1 = *reinterpret_cast<const float4*>(&As[kk][64 + ty * 4]);
            float4 b  = *reinterpret_cast<const float4*>(&Ws[kk][tx * 4]);
            float av[8] = {a0.x, a0.y, a0.z, a0.w, a1.x, a1.y, a1.z, a1.w};
            float bv[4] = {b.x, b.y, b.z, b.w};
#pragma unroll
            for (int i = 0; i < 8; i++)
#pragma unroll
                for (int j = 0; j < 4; j++)
                    acc[i][j] += av[i] * bv[j];
        }
        __syncthreads();
    }
    float4 bs = *reinterpret_cast<const float4*>(&bias[bn + tx * 4]);
#pragma unroll
    for (int i = 0; i < 8; i++) {
        int m = bm + ((i < 4) ? (ty * 4 + i) : (64 + ty * 4 + i - 4));
        float4 o = make_float4(acc[i][0] + bs.x, acc[i][1] + bs.y,
                               acc[i][2] + bs.z, acc[i][3] + bs.w);
        *reinterpret_cast<float4*>(&C[(size_t)m * N + bn + tx * 4]) = o;
    }
}

// Fused QKV: z selects which projection. Same core.
__global__ __launch_bounds__(256) void qkv_kernel(
    const float* __restrict__ Q, const float* __restrict__ K,
    const float* __restrict__ V,
    const float* __restrict__ Wq, const float* __restrict__ Wk,
    const float* __restrict__ Wv,
    const float* __restrict__ bq, const float* __restrict__ bk,
    const float* __restrict__ bv,
    float* __restrict__ q, float* __restrict__ k, float* __restrict__ v)
{
    __shared__ float As[16][132];
    __shared__ float Ws[16][68];
    const float *A, *W, *bias;
    float* C;
    if (blockIdx.z == 0)      { A = Q; W = Wq; bias = bq; C = q; }
    else if (blockIdx.z == 1) { A = K; W = Wk; bias = bk; C = k; }
    else                      { A = V; W = Wv; bias = bv; C = v; }

    const int tid = threadIdx.x;
    const int bm = blockIdx.y * 128, bn = blockIdx.x * 64;
    const int ty = tid >> 4, tx = tid & 15;
    float acc[8][4] = {};

    for (int k0 = 0; k0 < DM; k0 += 16) {
#pragma unroll
        for (int r = 0; r < 2; r++) {
            int idx = tid + r * 256;
            int m = idx >> 2, k4 = idx & 3;
            float4 t = *reinterpret_cast<const float4*>(
                &A[(size_t)(bm + m) * DM + k0 + k4 * 4]);
            As[k4 * 4 + 0][m] = t.x;
            As[k4 * 4 + 1][m] = t.y;
            As[k4 * 4 + 2][m] = t.z;
            As[k4 * 4 + 3][m] = t.w;
        }
        {
            int kk = tid >> 4, n4 = tid & 15;
            *reinterpret_cast<float4*>(&Ws[kk][n4 * 4]) =
                *reinterpret_cast<const float4*>(
                    &W[(size_t)(k0 + kk) * HD + bn + n4 * 4]);
        }
        __syncthreads();
#pragma unroll
        for (int kk = 0; kk < 16; kk++) {
            float4 a0 = *reinterpret_cast<const float4*>(&As[kk][ty * 4]);
            float4 a1 = *reinterpret_cast<const float4*>(&As[kk][64 + ty * 4]);
            float4 b  = *reinterpret_cast<const float4*>(&Ws[kk][tx * 4]);
            float av[8] = {a0.x, a0.y, a0.z, a0.w, a1.x, a1.y, a1.z, a1.w};
            float bv[4] = {b.x, b.y, b.z, b.w};
#pragma unroll
            for (int i = 0; i < 8; i++)
#pragma unroll
                for (int j = 0; j < 4; j++)
                    acc[i][j] += av[i] * bv[j];
        }
        __syncthreads();
    }
    float4 bs = *reinterpret_cast<const float4*>(&bias[bn + tx * 4]);
#pragma unroll
    for (int i = 0; i < 8; i++) {
        int m = bm + ((i < 4) ? (ty * 4 + i) : (64 + ty * 4 + i - 4));
        float4 o = make_float4(acc[i][0] + bs.x, acc[i][1] + bs.y,
                               acc[i][2] + bs.z, acc[i][3] + bs.w);
        *reinterpret_cast<float4*>(&C[(size_t)m * HD + bn + tx * 4]) = o;
    }
}

// ---------------------------------------------------------------------------
// Scores: S[i,j] = tanh(dot(q_i,k_j)/8)*10, masked -> -10. Writes raw clipped
// scores to attn AND accumulates per-row sum(exp(s)) into g_rowsum (atomics).
// 128x128 tile, 8x8 per thread, full DK=64 preloaded in dynamic smem, 1 sync.
// ---------------------------------------------------------------------------
__global__ __launch_bounds__(256) void scores_kernel(
    const float* __restrict__ q, const float* __restrict__ k,
    const int* __restrict__ mask, float* __restrict__ attn,
    float* __restrict__ rowsum)
{
    extern __shared__ float sm[];
    float* Qs = sm;                 // [64][132]  (d-major, i inner)
    float* Ks = sm + 64 * 132;      // [64][132]
    const int bh = blockIdx.z;
    const int b = bh >> 1, h = bh & 1;
    const int i0 = blockIdx.y * 128, j0 = blockIdx.x * 128;
    const int tid = threadIdx.x;
    const int ty = tid >> 4, tx = tid & 15;

#pragma unroll
    for (int r = 0; r < 8; r++) {           // 2048 f4 per tensor
        int idx = tid + r * 256;
        int k4q = idx & 3, i = (idx >> 2) & 127, cq = idx >> 9;
        int dbase = cq * 16 + k4q * 4;
        float4 tq = *reinterpret_cast<const float4*>(
            &q[(size_t)(b * LL + i0 + i) * HD + h * DK + dbase]);
        Qs[(dbase + 0) * 132 + i] = tq.x;
        Qs[(dbase + 1) * 132 + i] = tq.y;
        Qs[(dbase + 2) * 132 + i] = tq.z;
        Qs[(dbase + 3) * 132 + i] = tq.w;
        float4 tk = *reinterpret_cast<const float4*>(
            &k[(size_t)(b * LL + j0 + i) * HD + h * DK + dbase]);
        Ks[(dbase + 0) * 132 + i] = tk.x;
        Ks[(dbase + 1) * 132 + i] = tk.y;
        Ks[(dbase + 2) * 132 + i] = tk.z;
        Ks[(dbase + 3) * 132 + i] = tk.w;
    }
    __syncthreads();

    float acc[8][8] = {};
#pragma unroll
    for (int kk = 0; kk < 64; kk++) {
        float4 a0 = *reinterpret_cast<const float4*>(&Qs[kk * 132 + ty * 4]);
        float4 a1 = *reinterpret_cast<const float4*>(&Qs[kk * 132 + 64 + ty * 4]);
        float4 b0 = *reinterpret_cast<const float4*>(&Ks[kk * 132 + tx * 4]);
        float4 b1 = *reinterpret_cast<const float4*>(&Ks[kk * 132 + 64 + tx * 4]);
        float av[8] = {a0.x, a0.y, a0.z, a0.w, a1.x, a1.y, a1.z, a1.w};
        float bv[8] = {b0.x, b0.y, b0.z, b0.w, b1.x, b1.y, b1.z, b1.w};
#pragma unroll
        for (int i = 0; i < 8; i++)
#pragma unroll
            for (int j = 0; j < 8; j++)
                acc[i][j] += av[i] * bv[j];
    }

    const int jj0 = j0 + tx * 4;
    const int jj1 = j0 + 64 + tx * 4;
    int4 m0 = *reinterpret_cast<const int4*>(&mask[b * LL + jj0]);
    int4 m1 = *reinterpret_cast<const int4*>(&mask[b * LL + jj1]);
    const int msk[8] = {m0.x, m0.y, m0.z, m0.w, m1.x, m1.y, m1.z, m1.w};
#pragma unroll
    for (int i = 0; i < 8; i++) {
        int ii = i0 + ((i < 4) ? (ty * 4 + i) : (64 + ty * 4 + i - 4));
        float w[8];
#pragma unroll
        for (int j = 0; j < 8; j++)
            w[j] = msk[j] ? -10.0f : fast_tanh(acc[i][j] * 0.125f) * 10.0f;
        float* row = &attn[((size_t)bh * LL + ii) * LL];
        *reinterpret_cast<float4*>(&row[jj0]) = make_float4(w[0], w[1], w[2], w[3]);
        *reinterpret_cast<float4*>(&row[jj1]) = make_float4(w[4], w[5], w[6], w[7]);
        // per-row exp-sum over this thread's 8 cols, reduce across tx (16 lanes)
        float rs = __expf(w[0]) + __expf(w[1]) + __expf(w[2]) + __expf(w[3])
                 + __expf(w[4]) + __expf(w[5]) + __expf(w[6]) + __expf(w[7]);
#pragma unroll
        for (int o = 8; o; o >>= 1) rs += __shfl_xor_sync(0xffffffffu, rs, o);
        if (tx == 0) atomicAdd(&rowsum[bh * LL + ii], rs);
    }
}

// ---------------------------------------------------------------------------
// av: reads raw scores, w = s - lse[row]; writes w back to attn (final
// log-softmax output) and computes oh[i,d] = sum_j w * v[j,d].
// 64(i) x 64(d) tile, 4x4 per thread, BK=32.
// ---------------------------------------------------------------------------
__global__ __launch_bounds__(256) void av_kernel(
    float* __restrict__ attn, const float* __restrict__ v,
    const float* __restrict__ lse, float* __restrict__ oh)
{
    __shared__ float As[32][68];   // [j][i]
    __shared__ float Vs[32][68];   // [j][d]
    __shared__ float lse_s[64];
    const int bh = blockIdx.y;
    const int b = bh >> 1, h = bh & 1;
    const int i0 = blockIdx.x * 64;
    const int tid = threadIdx.x;
    const int ty = tid >> 4, tx = tid & 15;

    if (tid < 64) lse_s[tid] = lse[bh * LL + i0 + tid];
    __syncthreads();

    float acc[4][4] = {};
    for (int k0 = 0; k0 < LL; k0 += 32) {
#pragma unroll
        for (int r = 0; r < 2; r++) {
            int idx = tid + r * 256;      // 512 f4: 64 rows x 8 f4
            int i = idx >> 3, j4 = idx & 7;
            float* gp = &attn[((size_t)bh * LL + i0 + i) * LL + k0 + j4 * 4];
            float4 t = *reinterpret_cast<const float4*>(gp);
            float l = lse_s[i];
            t.x -= l; t.y -= l; t.z -= l; t.w -= l;
            *reinterpret_cast<float4*>(gp) = t;          // final attn out
            As[j4 * 4 + 0][i] = t.x;
            As[j4 * 4 + 1][i] = t.y;
            As[j4 * 4 + 2][i] = t.z;
            As[j4 * 4 + 3][i] = t.w;
        }
#pragma unroll
        for (int r = 0; r < 2; r++) {
            int idx = tid + r * 256;      // 512 f4: 32 rows x 16 f4
            int jj = idx >> 4, d4 = idx & 15;
            *reinterpret_cast<float4*>(&Vs[jj][d4 * 4]) =
                *reinterpret_cast<const float4*>(
                    &v[(size_t)(b * LL + k0 + jj) * HD + h * DK + d4 * 4]);
        }
        __syncthreads();
#pragma unroll
        for (int kk = 0; kk < 32; kk++) {
            float4 a = *reinterpret_cast<const float4*>(&As[kk][ty * 4]);
            float4 bb = *reinterpret_cast<const float4*>(&Vs[kk][tx * 4]);
            float av[4] = {a.x, a.y, a.z, a.w};
            float bv[4] = {bb.x, bb.y, bb.z, bb.w};
#pragma unroll
            for (int i = 0; i < 4; i++)
#pragma unroll
                for (int j = 0; j < 4; j++)
                    acc[i][j] += av[i] * bv[j];
        }
        __syncthreads();
    }
#pragma unroll
    for (int i = 0; i < 4; i++) {
        int ii = i0 + ty * 4 + i;
        float4 o = make_float4(acc[i][0], acc[i][1], acc[i][2], acc[i][3]);
        *reinterpret_cast<float4*>(
            &oh[(size_t)(b * LL + ii) * HD + h * DK + tx * 4]) = o;
    }
}

// ---------------------------------------------------------------------------
extern "C" void kernel_launch(void* const* d_in, const int* in_sizes, int n_in,
                              void* d_out, int out_size)
{
    const float* Q  = (const float*)d_in[0];
    const float* K  = (const float*)d_in[1];
    const float* V  = (const float*)d_in[2];
    const int*   mask = (const int*)d_in[3];
    const float* Wq = (const float*)d_in[4];
    const float* bq = (const float*)d_in[5];
    const float* Wk = (const float*)d_in[6];
    const float* bk = (const float*)d_in[7];
    const float* Wv = (const float*)d_in[8];
    const float* bv = (const float*)d_in[9];
    const float* Wo = (const float*)d_in[10];
    const float* bo = (const float*)d_in[11];

    float* out  = (float*)d_out;          // [B, Lq, 512]
    float* attn = out + OUT0;             // [B, H, Lq, Lk]

    float *q, *k, *v, *oh, *rs;
    cudaGetSymbolAddress((void**)&q,  g_q);
    cudaGetSymbolAddress((void**)&k,  g_k);
    cudaGetSymbolAddress((void**)&v,  g_v);
    cudaGetSymbolAddress((void**)&oh, g_oh);
    cudaGetSymbolAddress((void**)&rs, g_rowsum);

    const int M = BB * LL;                // 8192
    const int SCORES_SMEM = 2 * 64 * 132 * 4;   // 67584 B
    cudaFuncSetAttribute(scores_kernel,
                         cudaFuncAttributeMaxDynamicSharedMemorySize, SCORES_SMEM);

    // 0) zero the rowsum accumulator
    zero_rowsum_kernel<<<NROWS / 256, 256>>>(rs);

    // 1) fused projections: [8192,512] @ [512,128] x3
    dim3 gp(HD / 64, M / 128, 3);
    qkv_kernel<<<gp, 256>>>(Q, K, V, Wq, Wk, Wv, bq, bk, bv, q, k, v);

    // 2) scores + tanh clip + mask -> attn (raw) + rowsum atomics
    dim3 gs(LL / 128, LL / 128, BB * NH);
    scores_kernel<<<gs, 256, SCORES_SMEM>>>(q, k, mask, attn, rs);

    // 3) rowsum -> lse
    lse_kernel<<<NROWS / 256, 256>>>(rs);

    // 4) attn = s - lse (written back) ; oh = attn @ v
    dim3 ga(LL / 64, BB * NH);
    av_kernel<<<ga, 256>>>(attn, v, rs, oh);

    // 5) out = oh @ Wo + bo : [8192,128] @ [128,512]
    dim3 go(DM / 64, M / 128);
    gemm_bias_kernel<<<go, 256>>>(oh, Wo, bo, out, M, DM, HD);
}